// round 13
// baseline (speedup 1.0000x reference)
#include <cuda_runtime.h>
#include <math.h>
#include <stdint.h>

#define C_DIM 2048
#define E_DIM 64
#define TM    64
#define NTHR  256
#define NKT   (C_DIM / 16)      // 128 k16 tiles
#define HKT   (NKT / 2)         // 64 tile-pairs (two K halves each)
#define AMB_CAP 65536
#define TAU   1e-5f

__device__ float    g_colsq[E_DIM];
__device__ unsigned g_amb_count;
__device__ unsigned g_amb_list[AMB_CAP];
// B fragments grouped by tile-pair: [tt][half][j][lane] = uint4{hiw0,hiw1,low0,low1}
__device__ unsigned g_Bfrag[NKT * 8 * 32 * 4];

// ---------------- helpers ----------------
__device__ __forceinline__ unsigned smem_u32(const void* p) {
    unsigned a;
    asm("{ .reg .u64 t; cvta.to.shared.u64 t, %1; cvt.u32.u64 %0, t; }"
        : "=r"(a) : "l"(p));
    return a;
}
__device__ __forceinline__ unsigned pack_bf16x2(float lo, float hi) {
    unsigned r;
    asm("cvt.rn.bf16x2.f32 %0, %1, %2;" : "=r"(r) : "f"(hi), "f"(lo));
    return r;
}
__device__ __forceinline__ float lo_f(unsigned u) { return __uint_as_float(u << 16); }
__device__ __forceinline__ float hi_f(unsigned u) { return __uint_as_float(u & 0xFFFF0000u); }

__device__ __forceinline__ void mma16816(float& d0, float& d1, float& d2, float& d3,
                                         unsigned a0, unsigned a1, unsigned a2, unsigned a3,
                                         unsigned b0, unsigned b1) {
    asm volatile(
        "mma.sync.aligned.m16n8k16.row.col.f32.bf16.bf16.f32 "
        "{%0,%1,%2,%3}, {%4,%5,%6,%7}, {%8,%9}, {%0,%1,%2,%3};"
        : "+f"(d0), "+f"(d1), "+f"(d2), "+f"(d3)
        : "r"(a0), "r"(a1), "r"(a2), "r"(a3), "r"(b0), "r"(b1));
}
__device__ __forceinline__ void cp32(unsigned dst, const void* src) {
    asm volatile("cp.async.cg.shared.global [%0], [%1], 16;"
                 :: "r"(dst), "l"(src) : "memory");
    asm volatile("cp.async.cg.shared.global [%0], [%1], 16;"
                 :: "r"(dst + 16), "l"((const char*)src + 16) : "memory");
}
#define CP_COMMIT() asm volatile("cp.async.commit_group;" ::: "memory")
#define CP_WAIT(n)  asm volatile("cp.async.wait_group %0;" :: "n"(n) : "memory")

// ---------------------------------------------------------------------------
// Kernel 0: reset.
// ---------------------------------------------------------------------------
__global__ void zero_kernel() {
    if (threadIdx.x < E_DIM) g_colsq[threadIdx.x] = 0.f;
    if (threadIdx.x == 0) g_amb_count = 0;
}

// ---------------------------------------------------------------------------
// Kernel 1: coalesced column sum-of-squares of sim (C x E).
// ---------------------------------------------------------------------------
__global__ void colsum_kernel(const float* __restrict__ sim) {
    __shared__ float part[4][E_DIM];
    const int col  = threadIdx.x & 63;
    const int rg   = threadIdx.x >> 6;
    const int base = blockIdx.x * 32;
    float s = 0.f;
#pragma unroll
    for (int j = 0; j < 8; ++j) {
        float v = sim[(size_t)(base + rg + j * 4) * E_DIM + col];
        s = fmaf(v, v, s);
    }
    part[rg][col] = s;
    __syncthreads();
    if (threadIdx.x < E_DIM) {
        float t = part[0][threadIdx.x] + part[1][threadIdx.x]
                + part[2][threadIdx.x] + part[3][threadIdx.x];
        atomicAdd(&g_colsq[threadIdx.x], t);
    }
}

// ---------------------------------------------------------------------------
// Kernel 2: pack B into mma.sync col-major fragments, bf16 hi/lo split,
// grouped by tile-pair [tt][half].
// ---------------------------------------------------------------------------
__global__ void prepb_kernel(const float* __restrict__ sim) {
    int tid = blockIdx.x * 256 + threadIdx.x;
    int t = tid >> 5, l = tid & 31;        // t = k16-tile 0..127
    int tt = t & (HKT - 1), half = t >> 6;
    int k0 = t * 16 + (l & 3) * 2;
    int nb = l >> 2;
#pragma unroll
    for (int j = 0; j < 8; ++j) {
        int n = j * 8 + nb;
        float x0 = sim[(size_t)k0 * E_DIM + n];
        float x1 = sim[(size_t)(k0 + 1) * E_DIM + n];
        float y0 = sim[(size_t)(k0 + 8) * E_DIM + n];
        float y1 = sim[(size_t)(k0 + 9) * E_DIM + n];
        unsigned h0 = pack_bf16x2(x0, x1);
        unsigned h1 = pack_bf16x2(y0, y1);
        unsigned l0 = pack_bf16x2(x0 - lo_f(h0), x1 - hi_f(h0));
        unsigned l1 = pack_bf16x2(y0 - lo_f(h1), y1 - hi_f(h1));
        unsigned* dst = g_Bfrag + ((size_t)((tt * 2 + half) * 8 + j) * 32 + l) * 4;
        dst[0] = h0; dst[1] = h1; dst[2] = l0; dst[3] = l1;
    }
}

// ---------------------------------------------------------------------------
// Kernel 3: gating GEMM, mma.sync bf16 3-pass split.
//   8 warps: warp w -> rows [(w&3)*16,+16), K half (w>>2). 64 iterations.
//   B: cp.async 4-slot smem ring, ONE __syncthreads per tile.
//   A: gmem->reg 2-deep pipeline, fused row sumsq.
// ---------------------------------------------------------------------------
__global__ __launch_bounds__(NTHR)
void gating_kernel(const float* __restrict__ x,
                   const float* __restrict__ gates,
                   const float* __restrict__ temp,
                   const float* __restrict__ emask,
                   float* __restrict__ out,
                   int N)
{
    __shared__ __align__(16) unsigned Bs[4][2 * 8 * 32 * 4];  // 4 slots x 8KB
    __shared__ float Lg[TM][E_DIM + 4];
    __shared__ float rowsqS[2][TM];
    __shared__ float riS[TM];
    __shared__ float cfS[E_DIM], gthS[E_DIM];

    const int tid  = threadIdx.x;
    const int wid  = tid >> 5;
    const int lane = tid & 31;
    const int wq   = wid & 3;
    const int kg   = wid >> 2;
    const int row0 = blockIdx.x * TM;

    if (tid < E_DIM) {
        cfS[tid]  = (1.0f / fmaxf(sqrtf(g_colsq[tid]), 1e-12f)) * emask[tid];
        gthS[tid] = gates[tid] * (1.0f / (1.0f + expf(-temp[0])));
    }

    const int gr = lane >> 2;
    const int gq = (lane & 3) * 2;
    const int rA = wq * 16 + gr;
    const int r0g = min(row0 + rA,     N - 1);
    const int r8g = min(row0 + rA + 8, N - 1);
    const float* aptr0 = x + (size_t)r0g * C_DIM + kg * (HKT * 16) + gq;
    const float* aptr8 = x + (size_t)r8g * C_DIM + kg * (HKT * 16) + gq;

    // cp.async mapping: thread copies 32B of the 8KB tile-pair block
    const unsigned sdst[4] = {
        smem_u32(&Bs[0][0]) + (unsigned)tid * 32,
        smem_u32(&Bs[1][0]) + (unsigned)tid * 32,
        smem_u32(&Bs[2][0]) + (unsigned)tid * 32,
        smem_u32(&Bs[3][0]) + (unsigned)tid * 32 };
    const unsigned* bsrc = g_Bfrag + (size_t)tid * 8;   // + tt*2048

    float acc[8][4];
#pragma unroll
    for (int j = 0; j < 8; ++j)
#pragma unroll
        for (int c = 0; c < 4; ++c) acc[j][c] = 0.f;

    // prologue: B tiles 0,1,2 in flight
    cp32(sdst[0], bsrc);            CP_COMMIT();
    cp32(sdst[1], bsrc + 2048);     CP_COMMIT();
    cp32(sdst[2], bsrc + 4096);     CP_COMMIT();

    // A: 2-deep register pipeline
    float2 s00[2], s01[2], s10[2], s11[2];
    s00[0] = *(const float2*)(aptr0);      s01[0] = *(const float2*)(aptr0 + 8);
    s10[0] = *(const float2*)(aptr8);      s11[0] = *(const float2*)(aptr8 + 8);
    s00[1] = *(const float2*)(aptr0 + 16); s01[1] = *(const float2*)(aptr0 + 24);
    s10[1] = *(const float2*)(aptr8 + 16); s11[1] = *(const float2*)(aptr8 + 24);
    float ssa = 0.f, ssb = 0.f;

#pragma unroll 1
    for (int tt = 0; tt < HKT; ++tt) {
        // tile tt ready when <= min(2, HKT-1-tt) newer groups pending
        if (tt < HKT - 2)      CP_WAIT(2);
        else if (tt == HKT - 2) CP_WAIT(1);
        else                    CP_WAIT(0);
        __syncthreads();                       // all warps done with slot (tt+3)%4
        if (tt + 3 < HKT) {
            cp32(sdst[(tt + 3) & 3], bsrc + (size_t)(tt + 3) * 2048);
            CP_COMMIT();
        }

        const int cur = tt & 1;
        float2 p00 = s00[cur], p01 = s01[cur], p10 = s10[cur], p11 = s11[cur];
        if (tt + 2 < HKT) {                    // A prefetch t+2
            const float* a0 = aptr0 + (tt + 2) * 16;
            const float* a8 = aptr8 + (tt + 2) * 16;
            s00[cur] = *(const float2*)(a0); s01[cur] = *(const float2*)(a0 + 8);
            s10[cur] = *(const float2*)(a8); s11[cur] = *(const float2*)(a8 + 8);
        }

        // convert A: bf16 hi/lo + fused row sumsq
        ssa = fmaf(p00.x, p00.x, ssa); ssa = fmaf(p00.y, p00.y, ssa);
        ssa = fmaf(p01.x, p01.x, ssa); ssa = fmaf(p01.y, p01.y, ssa);
        ssb = fmaf(p10.x, p10.x, ssb); ssb = fmaf(p10.y, p10.y, ssb);
        ssb = fmaf(p11.x, p11.x, ssb); ssb = fmaf(p11.y, p11.y, ssb);
        unsigned aH0 = pack_bf16x2(p00.x, p00.y);
        unsigned aH1 = pack_bf16x2(p10.x, p10.y);
        unsigned aH2 = pack_bf16x2(p01.x, p01.y);
        unsigned aH3 = pack_bf16x2(p11.x, p11.y);
        unsigned aL0 = pack_bf16x2(p00.x - lo_f(aH0), p00.y - hi_f(aH0));
        unsigned aL1 = pack_bf16x2(p10.x - lo_f(aH1), p10.y - hi_f(aH1));
        unsigned aL2 = pack_bf16x2(p01.x - lo_f(aH2), p01.y - hi_f(aH2));
        unsigned aL3 = pack_bf16x2(p11.x - lo_f(aH3), p11.y - hi_f(aH3));

        const uint4* bb = (const uint4*)Bs[tt & 3] + kg * 256 + lane;
#pragma unroll
        for (int j = 0; j < 8; ++j) {
            uint4 b = bb[j * 32];
            mma16816(acc[j][0], acc[j][1], acc[j][2], acc[j][3],
                     aH0, aH1, aH2, aH3, b.x, b.y);   // hi*Bhi
            mma16816(acc[j][0], acc[j][1], acc[j][2], acc[j][3],
                     aH0, aH1, aH2, aH3, b.z, b.w);   // hi*Blo
            mma16816(acc[j][0], acc[j][1], acc[j][2], acc[j][3],
                     aL0, aL1, aL2, aL3, b.x, b.y);   // lo*Bhi
        }
    }

    // per-(row, K-half) sumsq
    ssa += __shfl_xor_sync(0xffffffffu, ssa, 1);
    ssa += __shfl_xor_sync(0xffffffffu, ssa, 2);
    ssb += __shfl_xor_sync(0xffffffffu, ssb, 1);
    ssb += __shfl_xor_sync(0xffffffffu, ssb, 2);
    if ((lane & 3) == 0) {
        rowsqS[kg][rA]     = ssa;
        rowsqS[kg][rA + 8] = ssb;
    }

    // cross-K-half accumulator reduce through Lg
    if (kg == 0) {
#pragma unroll
        for (int j = 0; j < 8; ++j) {
            int c0 = j * 8 + gq;
            Lg[rA][c0]         = acc[j][0];
            Lg[rA][c0 + 1]     = acc[j][1];
            Lg[rA + 8][c0]     = acc[j][2];
            Lg[rA + 8][c0 + 1] = acc[j][3];
        }
    }
    __syncthreads();
    if (kg == 1) {
#pragma unroll
        for (int j = 0; j < 8; ++j) {
            int c0 = j * 8 + gq;
            Lg[rA][c0]         += acc[j][0];
            Lg[rA][c0 + 1]     += acc[j][1];
            Lg[rA + 8][c0]     += acc[j][2];
            Lg[rA + 8][c0 + 1] += acc[j][3];
        }
    }
    if (tid < TM)
        riS[tid] = 1.0f / fmaxf(sqrtf(rowsqS[0][tid] + rowsqS[1][tid]), 1e-12f);
    __syncthreads();

    // epilogue: normalize, mask, ambiguity flag, coalesced stores
    const size_t NE = (size_t)N * E_DIM;
#pragma unroll
    for (int it = 0; it < (TM * E_DIM) / (4 * NTHR); ++it) {   // 4 iters
        int f4  = tid + it * NTHR;
        int row = f4 >> 4;
        int cc  = (f4 & 15) * 4;
        int grow = row0 + row;
        const float ri = riS[row];
        float lg[4], m[4];
#pragma unroll
        for (int c = 0; c < 4; ++c) {
            lg[c] = Lg[row][cc + c] * ri * cfS[cc + c];
            float z = lg[c] - gthS[cc + c];
            m[c] = (z > 0.f) ? 1.0f : 0.0f;
            if (fabsf(z) < TAU && grow < N) {
                unsigned idx = atomicAdd(&g_amb_count, 1u);
                if (idx < AMB_CAP)
                    g_amb_list[idx] = ((unsigned)grow << 8) | (unsigned)(cc + c);
            }
        }
        if (grow < N) {
            *(float4*)&out[(size_t)grow * E_DIM + cc] =
                make_float4(m[0], m[1], m[2], m[3]);
            *(float4*)&out[NE + (size_t)grow * E_DIM + cc] =
                make_float4(lg[0], lg[1], lg[2], lg[3]);
        }
    }
}

// ---------------------------------------------------------------------------
// Kernel 4: fp64 refinement of near-boundary mask entries (x4 ILP).
// ---------------------------------------------------------------------------
__global__ __launch_bounds__(128)
void refine_kernel(const float* __restrict__ x,
                   const float* __restrict__ sim,
                   const float* __restrict__ gates,
                   const float* __restrict__ temp,
                   const float* __restrict__ emask,
                   float* __restrict__ out)
{
    unsigned cnt = g_amb_count;
    if (cnt > AMB_CAP) cnt = AMB_CAP;
    const int lane  = threadIdx.x & 31;
    const int warp  = (blockIdx.x * blockDim.x + threadIdx.x) >> 5;
    const int nwarp = (gridDim.x * blockDim.x) >> 5;

    for (unsigned i = warp; i < cnt; i += nwarp) {
        unsigned pk = g_amb_list[i];
        int rr = (int)(pk >> 8);
        int e  = (int)(pk & 0xFF);
        const float* ar = x + (size_t)rr * C_DIM;
        double d0 = 0, d1 = 0, d2 = 0, d3 = 0;
        double na0 = 0, na1 = 0, na2 = 0, na3 = 0;
        double nb0 = 0, nb1 = 0, nb2 = 0, nb3 = 0;
#pragma unroll 1
        for (int k = lane; k < C_DIM; k += 128) {
            double a0 = ar[k],      b0 = sim[(size_t)(k)      * E_DIM + e];
            double a1 = ar[k + 32], b1 = sim[(size_t)(k + 32) * E_DIM + e];
            double a2 = ar[k + 64], b2 = sim[(size_t)(k + 64) * E_DIM + e];
            double a3 = ar[k + 96], b3 = sim[(size_t)(k + 96) * E_DIM + e];
            d0 = fma(a0, b0, d0); na0 = fma(a0, a0, na0); nb0 = fma(b0, b0, nb0);
            d1 = fma(a1, b1, d1); na1 = fma(a1, a1, na1); nb1 = fma(b1, b1, nb1);
            d2 = fma(a2, b2, d2); na2 = fma(a2, a2, na2); nb2 = fma(b2, b2, nb2);
            d3 = fma(a3, b3, d3); na3 = fma(a3, a3, na3); nb3 = fma(b3, b3, nb3);
        }
        double d  = (d0 + d1) + (d2 + d3);
        double na = (na0 + na1) + (na2 + na3);
        double nb = (nb0 + nb1) + (nb2 + nb3);
#pragma unroll
        for (int off = 16; off; off >>= 1) {
            d  += __shfl_xor_sync(0xffffffffu, d,  off);
            na += __shfl_xor_sync(0xffffffffu, na, off);
            nb += __shfl_xor_sync(0xffffffffu, nb, off);
        }
        if (lane == 0) {
            double t     = (double)temp[0];
            double scale = 1.0 / (1.0 + exp(-t));
            double lgv = d / fmax(sqrt(na), 1e-12) / fmax(sqrt(nb), 1e-12);
            lgv *= (double)emask[e];
            double z = lgv - (double)gates[e] * scale;
            out[(size_t)rr * E_DIM + e] = (z > 0.0) ? 1.0f : 0.0f;
        }
    }
}

// ---------------------------------------------------------------------------
// Kernel 5: fallback top-k on rows whose FINAL mask is all-zero.
// ---------------------------------------------------------------------------
__global__ __launch_bounds__(256)
void fbfix_kernel(const int* __restrict__ minkp, float* __restrict__ out, int N)
{
    const int lane = threadIdx.x & 31;
    const int row  = (blockIdx.x * blockDim.x + threadIdx.x) >> 5;
    if (row >= N) return;
    float m0 = out[(size_t)row * E_DIM + lane];
    float m1 = out[(size_t)row * E_DIM + 32 + lane];
    unsigned act = __ballot_sync(0xffffffffu, m0 > 0.f)
                 | __ballot_sync(0xffffffffu, m1 > 0.f);
    if (act) return;

    int minK = minkp ? *minkp : 2;
    minK = min(max(minK, 0), E_DIM);
    const size_t NE = (size_t)N * E_DIM;
    float v0 = out[NE + (size_t)row * E_DIM + lane];
    float v1 = out[NE + (size_t)row * E_DIM + 32 + lane];
    bool c0 = false, c1 = false;
    for (int t = 0; t < minK; ++t) {
        float bv = -3.402823466e38f; int bi = 1 << 20;
        if (!c0) { bv = v0; bi = lane; }
        if (!c1 && (v1 > bv || (v1 == bv && lane + 32 < bi))) { bv = v1; bi = lane + 32; }
#pragma unroll
        for (int o = 16; o; o >>= 1) {
            float ov = __shfl_xor_sync(0xffffffffu, bv, o);
            int   oi = __shfl_xor_sync(0xffffffffu, bi, o);
            if (ov > bv || (ov == bv && oi < bi)) { bv = ov; bi = oi; }
        }
        if (bi == lane)      c0 = true;
        if (bi == lane + 32) c1 = true;
        if (lane == 0 && bi < E_DIM)
            out[(size_t)row * E_DIM + bi] = 1.0f;
    }
}

extern "C" void kernel_launch(void* const* d_in, const int* in_sizes, int n_in,
                              void* d_out, int out_size) {
    (void)out_size;
    const float* x     = (const float*)d_in[0];
    const float* sim   = (const float*)d_in[1];
    const float* gates = (const float*)d_in[2];
    const float* temp  = (const float*)d_in[3];
    const float* emask = (const float*)d_in[4];
    const int*   minkp = (n_in > 5) ? (const int*)d_in[5] : nullptr;

    int N = in_sizes[0] / C_DIM;

    zero_kernel<<<1, 128>>>();
    colsum_kernel<<<C_DIM / 32, 256>>>(sim);
    prepb_kernel<<<NKT * 32 / 256, 256>>>(sim);
    gating_kernel<<<(N + TM - 1) / TM, NTHR>>>(x, gates, temp, emask,
                                               (float*)d_out, N);
    refine_kernel<<<128, 128>>>(x, sim, gates, temp, emask, (float*)d_out);
    fbfix_kernel<<<(N * 32 + 255) / 256, 256>>>(minkp, (float*)d_out, N);
}

// round 14
// speedup vs baseline: 1.0020x; 1.0020x over previous
#include <cuda_runtime.h>
#include <math.h>
#include <stdint.h>

#define C_DIM 2048
#define E_DIM 64
#define TM    64
#define NTHR  256
#define NKT   (C_DIM / 16)      // 128 k16 tiles
#define HKT   (NKT / 2)         // 64 tile-pairs (two K halves each)
#define AMB_CAP 65536
#define TAU   1e-5f

__device__ float    g_colsq[E_DIM];
__device__ unsigned g_amb_count;
__device__ unsigned g_amb_list[AMB_CAP];
// B fragments grouped by tile-pair: [tt][half][j][lane] = uint4{hiw0,hiw1,low0,low1}
__device__ unsigned g_Bfrag[NKT * 8 * 32 * 4];

// ---------------- helpers ----------------
__device__ __forceinline__ unsigned smem_u32(const void* p) {
    unsigned a;
    asm("{ .reg .u64 t; cvta.to.shared.u64 t, %1; cvt.u32.u64 %0, t; }"
        : "=r"(a) : "l"(p));
    return a;
}
__device__ __forceinline__ unsigned pack_bf16x2(float lo, float hi) {
    unsigned r;
    asm("cvt.rn.bf16x2.f32 %0, %1, %2;" : "=r"(r) : "f"(hi), "f"(lo));
    return r;
}
__device__ __forceinline__ float lo_f(unsigned u) { return __uint_as_float(u << 16); }
__device__ __forceinline__ float hi_f(unsigned u) { return __uint_as_float(u & 0xFFFF0000u); }

__device__ __forceinline__ void mma16816(float& d0, float& d1, float& d2, float& d3,
                                         unsigned a0, unsigned a1, unsigned a2, unsigned a3,
                                         unsigned b0, unsigned b1) {
    asm volatile(
        "mma.sync.aligned.m16n8k16.row.col.f32.bf16.bf16.f32 "
        "{%0,%1,%2,%3}, {%4,%5,%6,%7}, {%8,%9}, {%0,%1,%2,%3};"
        : "+f"(d0), "+f"(d1), "+f"(d2), "+f"(d3)
        : "r"(a0), "r"(a1), "r"(a2), "r"(a3), "r"(b0), "r"(b1));
}
__device__ __forceinline__ void cp32(unsigned dst, const void* src) {
    asm volatile("cp.async.cg.shared.global [%0], [%1], 16;"
                 :: "r"(dst), "l"(src) : "memory");
    asm volatile("cp.async.cg.shared.global [%0], [%1], 16;"
                 :: "r"(dst + 16), "l"((const char*)src + 16) : "memory");
}
#define CP_COMMIT() asm volatile("cp.async.commit_group;" ::: "memory")
#define CP_WAIT(n)  asm volatile("cp.async.wait_group %0;" :: "n"(n) : "memory")

// ---------------------------------------------------------------------------
// Kernel 0: reset.
// ---------------------------------------------------------------------------
__global__ void zero_kernel() {
    if (threadIdx.x < E_DIM) g_colsq[threadIdx.x] = 0.f;
    if (threadIdx.x == 0) g_amb_count = 0;
}

// ---------------------------------------------------------------------------
// Kernel 1: coalesced column sum-of-squares of sim (C x E).
// ---------------------------------------------------------------------------
__global__ void colsum_kernel(const float* __restrict__ sim) {
    __shared__ float part[4][E_DIM];
    const int col  = threadIdx.x & 63;
    const int rg   = threadIdx.x >> 6;
    const int base = blockIdx.x * 32;
    float s = 0.f;
#pragma unroll
    for (int j = 0; j < 8; ++j) {
        float v = sim[(size_t)(base + rg + j * 4) * E_DIM + col];
        s = fmaf(v, v, s);
    }
    part[rg][col] = s;
    __syncthreads();
    if (threadIdx.x < E_DIM) {
        float t = part[0][threadIdx.x] + part[1][threadIdx.x]
                + part[2][threadIdx.x] + part[3][threadIdx.x];
        atomicAdd(&g_colsq[threadIdx.x], t);
    }
}

// ---------------------------------------------------------------------------
// Kernel 2: pack B into mma.sync col-major fragments, bf16 hi/lo split,
// grouped by tile-pair [tt][half].
// ---------------------------------------------------------------------------
__global__ void prepb_kernel(const float* __restrict__ sim) {
    int tid = blockIdx.x * 256 + threadIdx.x;
    int t = tid >> 5, l = tid & 31;        // t = k16-tile 0..127
    int tt = t & (HKT - 1), half = t >> 6;
    int k0 = t * 16 + (l & 3) * 2;
    int nb = l >> 2;
#pragma unroll
    for (int j = 0; j < 8; ++j) {
        int n = j * 8 + nb;
        float x0 = sim[(size_t)k0 * E_DIM + n];
        float x1 = sim[(size_t)(k0 + 1) * E_DIM + n];
        float y0 = sim[(size_t)(k0 + 8) * E_DIM + n];
        float y1 = sim[(size_t)(k0 + 9) * E_DIM + n];
        unsigned h0 = pack_bf16x2(x0, x1);
        unsigned h1 = pack_bf16x2(y0, y1);
        unsigned l0 = pack_bf16x2(x0 - lo_f(h0), x1 - hi_f(h0));
        unsigned l1 = pack_bf16x2(y0 - lo_f(h1), y1 - hi_f(h1));
        unsigned* dst = g_Bfrag + ((size_t)((tt * 2 + half) * 8 + j) * 32 + l) * 4;
        dst[0] = h0; dst[1] = h1; dst[2] = l0; dst[3] = l1;
    }
}

// ---------------------------------------------------------------------------
// Kernel 3: gating GEMM, mma.sync bf16 3-pass split.
//   8 warps: warp w -> rows [(w&3)*16,+16), K half (w>>2). 64 iterations.
//   B: cp.async 4-slot smem ring, ONE __syncthreads per tile.
//   A: gmem->reg 2-deep pipeline, fused row sumsq.
// ---------------------------------------------------------------------------
__global__ __launch_bounds__(NTHR)
void gating_kernel(const float* __restrict__ x,
                   const float* __restrict__ gates,
                   const float* __restrict__ temp,
                   const float* __restrict__ emask,
                   float* __restrict__ out,
                   int N)
{
    __shared__ __align__(16) unsigned Bs[4][2 * 8 * 32 * 4];  // 4 slots x 8KB
    __shared__ float Lg[TM][E_DIM + 4];
    __shared__ float rowsqS[2][TM];
    __shared__ float riS[TM];
    __shared__ float cfS[E_DIM], gthS[E_DIM];

    const int tid  = threadIdx.x;
    const int wid  = tid >> 5;
    const int lane = tid & 31;
    const int wq   = wid & 3;
    const int kg   = wid >> 2;
    const int row0 = blockIdx.x * TM;

    if (tid < E_DIM) {
        cfS[tid]  = (1.0f / fmaxf(sqrtf(g_colsq[tid]), 1e-12f)) * emask[tid];
        gthS[tid] = gates[tid] * (1.0f / (1.0f + expf(-temp[0])));
    }

    const int gr = lane >> 2;
    const int gq = (lane & 3) * 2;
    const int rA = wq * 16 + gr;
    const int r0g = min(row0 + rA,     N - 1);
    const int r8g = min(row0 + rA + 8, N - 1);
    const float* aptr0 = x + (size_t)r0g * C_DIM + kg * (HKT * 16) + gq;
    const float* aptr8 = x + (size_t)r8g * C_DIM + kg * (HKT * 16) + gq;

    // cp.async mapping: thread copies 32B of the 8KB tile-pair block
    const unsigned sdst[4] = {
        smem_u32(&Bs[0][0]) + (unsigned)tid * 32,
        smem_u32(&Bs[1][0]) + (unsigned)tid * 32,
        smem_u32(&Bs[2][0]) + (unsigned)tid * 32,
        smem_u32(&Bs[3][0]) + (unsigned)tid * 32 };
    const unsigned* bsrc = g_Bfrag + (size_t)tid * 8;   // + tt*2048

    float acc[8][4];
#pragma unroll
    for (int j = 0; j < 8; ++j)
#pragma unroll
        for (int c = 0; c < 4; ++c) acc[j][c] = 0.f;

    // prologue: B tiles 0,1,2 in flight
    cp32(sdst[0], bsrc);            CP_COMMIT();
    cp32(sdst[1], bsrc + 2048);     CP_COMMIT();
    cp32(sdst[2], bsrc + 4096);     CP_COMMIT();

    // A: 2-deep register pipeline
    float2 s00[2], s01[2], s10[2], s11[2];
    s00[0] = *(const float2*)(aptr0);      s01[0] = *(const float2*)(aptr0 + 8);
    s10[0] = *(const float2*)(aptr8);      s11[0] = *(const float2*)(aptr8 + 8);
    s00[1] = *(const float2*)(aptr0 + 16); s01[1] = *(const float2*)(aptr0 + 24);
    s10[1] = *(const float2*)(aptr8 + 16); s11[1] = *(const float2*)(aptr8 + 24);
    float ssa = 0.f, ssb = 0.f;

#pragma unroll 1
    for (int tt = 0; tt < HKT; ++tt) {
        // tile tt ready when <= min(2, HKT-1-tt) newer groups pending
        if (tt < HKT - 2)      CP_WAIT(2);
        else if (tt == HKT - 2) CP_WAIT(1);
        else                    CP_WAIT(0);
        __syncthreads();                       // all warps done with slot (tt+3)%4
        if (tt + 3 < HKT) {
            cp32(sdst[(tt + 3) & 3], bsrc + (size_t)(tt + 3) * 2048);
            CP_COMMIT();
        }

        const int cur = tt & 1;
        float2 p00 = s00[cur], p01 = s01[cur], p10 = s10[cur], p11 = s11[cur];
        if (tt + 2 < HKT) {                    // A prefetch t+2
            const float* a0 = aptr0 + (tt + 2) * 16;
            const float* a8 = aptr8 + (tt + 2) * 16;
            s00[cur] = *(const float2*)(a0); s01[cur] = *(const float2*)(a0 + 8);
            s10[cur] = *(const float2*)(a8); s11[cur] = *(const float2*)(a8 + 8);
        }

        // convert A: bf16 hi/lo + fused row sumsq
        ssa = fmaf(p00.x, p00.x, ssa); ssa = fmaf(p00.y, p00.y, ssa);
        ssa = fmaf(p01.x, p01.x, ssa); ssa = fmaf(p01.y, p01.y, ssa);
        ssb = fmaf(p10.x, p10.x, ssb); ssb = fmaf(p10.y, p10.y, ssb);
        ssb = fmaf(p11.x, p11.x, ssb); ssb = fmaf(p11.y, p11.y, ssb);
        unsigned aH0 = pack_bf16x2(p00.x, p00.y);
        unsigned aH1 = pack_bf16x2(p10.x, p10.y);
        unsigned aH2 = pack_bf16x2(p01.x, p01.y);
        unsigned aH3 = pack_bf16x2(p11.x, p11.y);
        unsigned aL0 = pack_bf16x2(p00.x - lo_f(aH0), p00.y - hi_f(aH0));
        unsigned aL1 = pack_bf16x2(p10.x - lo_f(aH1), p10.y - hi_f(aH1));
        unsigned aL2 = pack_bf16x2(p01.x - lo_f(aH2), p01.y - hi_f(aH2));
        unsigned aL3 = pack_bf16x2(p11.x - lo_f(aH3), p11.y - hi_f(aH3));

        const uint4* bb = (const uint4*)Bs[tt & 3] + kg * 256 + lane;
#pragma unroll
        for (int j = 0; j < 8; ++j) {
            uint4 b = bb[j * 32];
            mma16816(acc[j][0], acc[j][1], acc[j][2], acc[j][3],
                     aH0, aH1, aH2, aH3, b.x, b.y);   // hi*Bhi
            mma16816(acc[j][0], acc[j][1], acc[j][2], acc[j][3],
                     aH0, aH1, aH2, aH3, b.z, b.w);   // hi*Blo
            mma16816(acc[j][0], acc[j][1], acc[j][2], acc[j][3],
                     aL0, aL1, aL2, aL3, b.x, b.y);   // lo*Bhi
        }
    }

    // per-(row, K-half) sumsq
    ssa += __shfl_xor_sync(0xffffffffu, ssa, 1);
    ssa += __shfl_xor_sync(0xffffffffu, ssa, 2);
    ssb += __shfl_xor_sync(0xffffffffu, ssb, 1);
    ssb += __shfl_xor_sync(0xffffffffu, ssb, 2);
    if ((lane & 3) == 0) {
        rowsqS[kg][rA]     = ssa;
        rowsqS[kg][rA + 8] = ssb;
    }

    // cross-K-half accumulator reduce through Lg
    if (kg == 0) {
#pragma unroll
        for (int j = 0; j < 8; ++j) {
            int c0 = j * 8 + gq;
            Lg[rA][c0]         = acc[j][0];
            Lg[rA][c0 + 1]     = acc[j][1];
            Lg[rA + 8][c0]     = acc[j][2];
            Lg[rA + 8][c0 + 1] = acc[j][3];
        }
    }
    __syncthreads();
    if (kg == 1) {
#pragma unroll
        for (int j = 0; j < 8; ++j) {
            int c0 = j * 8 + gq;
            Lg[rA][c0]         += acc[j][0];
            Lg[rA][c0 + 1]     += acc[j][1];
            Lg[rA + 8][c0]     += acc[j][2];
            Lg[rA + 8][c0 + 1] += acc[j][3];
        }
    }
    if (tid < TM)
        riS[tid] = 1.0f / fmaxf(sqrtf(rowsqS[0][tid] + rowsqS[1][tid]), 1e-12f);
    __syncthreads();

    // epilogue: normalize, mask, ambiguity flag, coalesced stores
    const size_t NE = (size_t)N * E_DIM;
#pragma unroll
    for (int it = 0; it < (TM * E_DIM) / (4 * NTHR); ++it) {   // 4 iters
        int f4  = tid + it * NTHR;
        int row = f4 >> 4;
        int cc  = (f4 & 15) * 4;
        int grow = row0 + row;
        const float ri = riS[row];
        float lg[4], m[4];
#pragma unroll
        for (int c = 0; c < 4; ++c) {
            lg[c] = Lg[row][cc + c] * ri * cfS[cc + c];
            float z = lg[c] - gthS[cc + c];
            m[c] = (z > 0.f) ? 1.0f : 0.0f;
            if (fabsf(z) < TAU && grow < N) {
                unsigned idx = atomicAdd(&g_amb_count, 1u);
                if (idx < AMB_CAP)
                    g_amb_list[idx] = ((unsigned)grow << 8) | (unsigned)(cc + c);
            }
        }
        if (grow < N) {
            *(float4*)&out[(size_t)grow * E_DIM + cc] =
                make_float4(m[0], m[1], m[2], m[3]);
            *(float4*)&out[NE + (size_t)grow * E_DIM + cc] =
                make_float4(lg[0], lg[1], lg[2], lg[3]);
        }
    }
}

// ---------------------------------------------------------------------------
// Kernel 4: fp64 refinement of near-boundary mask entries (x4 ILP).
// ---------------------------------------------------------------------------
__global__ __launch_bounds__(128)
void refine_kernel(const float* __restrict__ x,
                   const float* __restrict__ sim,
                   const float* __restrict__ gates,
                   const float* __restrict__ temp,
                   const float* __restrict__ emask,
                   float* __restrict__ out)
{
    unsigned cnt = g_amb_count;
    if (cnt > AMB_CAP) cnt = AMB_CAP;
    const int lane  = threadIdx.x & 31;
    const int warp  = (blockIdx.x * blockDim.x + threadIdx.x) >> 5;
    const int nwarp = (gridDim.x * blockDim.x) >> 5;

    for (unsigned i = warp; i < cnt; i += nwarp) {
        unsigned pk = g_amb_list[i];
        int rr = (int)(pk >> 8);
        int e  = (int)(pk & 0xFF);
        const float* ar = x + (size_t)rr * C_DIM;
        double d0 = 0, d1 = 0, d2 = 0, d3 = 0;
        double na0 = 0, na1 = 0, na2 = 0, na3 = 0;
        double nb0 = 0, nb1 = 0, nb2 = 0, nb3 = 0;
#pragma unroll 1
        for (int k = lane; k < C_DIM; k += 128) {
            double a0 = ar[k],      b0 = sim[(size_t)(k)      * E_DIM + e];
            double a1 = ar[k + 32], b1 = sim[(size_t)(k + 32) * E_DIM + e];
            double a2 = ar[k + 64], b2 = sim[(size_t)(k + 64) * E_DIM + e];
            double a3 = ar[k + 96], b3 = sim[(size_t)(k + 96) * E_DIM + e];
            d0 = fma(a0, b0, d0); na0 = fma(a0, a0, na0); nb0 = fma(b0, b0, nb0);
            d1 = fma(a1, b1, d1); na1 = fma(a1, a1, na1); nb1 = fma(b1, b1, nb1);
            d2 = fma(a2, b2, d2); na2 = fma(a2, a2, na2); nb2 = fma(b2, b2, nb2);
            d3 = fma(a3, b3, d3); na3 = fma(a3, a3, na3); nb3 = fma(b3, b3, nb3);
        }
        double d  = (d0 + d1) + (d2 + d3);
        double na = (na0 + na1) + (na2 + na3);
        double nb = (nb0 + nb1) + (nb2 + nb3);
#pragma unroll
        for (int off = 16; off; off >>= 1) {
            d  += __shfl_xor_sync(0xffffffffu, d,  off);
            na += __shfl_xor_sync(0xffffffffu, na, off);
            nb += __shfl_xor_sync(0xffffffffu, nb, off);
        }
        if (lane == 0) {
            double t     = (double)temp[0];
            double scale = 1.0 / (1.0 + exp(-t));
            double lgv = d / fmax(sqrt(na), 1e-12) / fmax(sqrt(nb), 1e-12);
            lgv *= (double)emask[e];
            double z = lgv - (double)gates[e] * scale;
            out[(size_t)rr * E_DIM + e] = (z > 0.0) ? 1.0f : 0.0f;
        }
    }
}

// ---------------------------------------------------------------------------
// Kernel 5: fallback top-k on rows whose FINAL mask is all-zero.
// ---------------------------------------------------------------------------
__global__ __launch_bounds__(256)
void fbfix_kernel(const int* __restrict__ minkp, float* __restrict__ out, int N)
{
    const int lane = threadIdx.x & 31;
    const int row  = (blockIdx.x * blockDim.x + threadIdx.x) >> 5;
    if (row >= N) return;
    float m0 = out[(size_t)row * E_DIM + lane];
    float m1 = out[(size_t)row * E_DIM + 32 + lane];
    unsigned act = __ballot_sync(0xffffffffu, m0 > 0.f)
                 | __ballot_sync(0xffffffffu, m1 > 0.f);
    if (act) return;

    int minK = minkp ? *minkp : 2;
    minK = min(max(minK, 0), E_DIM);
    const size_t NE = (size_t)N * E_DIM;
    float v0 = out[NE + (size_t)row * E_DIM + lane];
    float v1 = out[NE + (size_t)row * E_DIM + 32 + lane];
    bool c0 = false, c1 = false;
    for (int t = 0; t < minK; ++t) {
        float bv = -3.402823466e38f; int bi = 1 << 20;
        if (!c0) { bv = v0; bi = lane; }
        if (!c1 && (v1 > bv || (v1 == bv && lane + 32 < bi))) { bv = v1; bi = lane + 32; }
#pragma unroll
        for (int o = 16; o; o >>= 1) {
            float ov = __shfl_xor_sync(0xffffffffu, bv, o);
            int   oi = __shfl_xor_sync(0xffffffffu, bi, o);
            if (ov > bv || (ov == bv && oi < bi)) { bv = ov; bi = oi; }
        }
        if (bi == lane)      c0 = true;
        if (bi == lane + 32) c1 = true;
        if (lane == 0 && bi < E_DIM)
            out[(size_t)row * E_DIM + bi] = 1.0f;
    }
}

extern "C" void kernel_launch(void* const* d_in, const int* in_sizes, int n_in,
                              void* d_out, int out_size) {
    (void)out_size;
    const float* x     = (const float*)d_in[0];
    const float* sim   = (const float*)d_in[1];
    const float* gates = (const float*)d_in[2];
    const float* temp  = (const float*)d_in[3];
    const float* emask = (const float*)d_in[4];
    const int*   minkp = (n_in > 5) ? (const int*)d_in[5] : nullptr;

    int N = in_sizes[0] / C_DIM;

    zero_kernel<<<1, 128>>>();
    colsum_kernel<<<C_DIM / 32, 256>>>(sim);
    prepb_kernel<<<NKT * 32 / 256, 256>>>(sim);
    gating_kernel<<<(N + TM - 1) / TM, NTHR>>>(x, gates, temp, emask,
                                               (float*)d_out, N);
    refine_kernel<<<128, 128>>>(x, sim, gates, temp, emask, (float*)d_out);
    fbfix_kernel<<<(N * 32 + 255) / 256, 256>>>(minkp, (float*)d_out, N);
}